// round 17
// baseline (speedup 1.0000x reference)
#include <cuda_runtime.h>
#include <math.h>

#define BB 16
#define TT 2048
#define DD 2048
#define CC 100

#define ALPHA 0.0005f
#define MARGIN 100.0f
#define EPS_C 1e-7f

#define FEAT_DCHUNK 64                        // floats per d-strip
#define FEAT_NDCH (DD / FEAT_DCHUNK)          // 32
#define FEAT_TILES (2 * BB * FEAT_NDCH)       // 1024
#define BTC_TILES 512                         // 32 tchunks(64t) x 16 b
#define NTILES (1 + FEAT_TILES + BTC_TILES)   // 1537 (tile 0 = BCE)

#define GRID_BLOCKS 1184                      // 148 SMs x 8 resident blocks

// ---------------- scratch (device globals; zero-init at load) ----------------
// Invariant: zero at kernel_launch entry; final_kernel re-zeros after reading.
__device__ float g_n2[2 * BB];          // squared norms of mean features
__device__ float g_sq[BB * CC];         // sum_t (sup - pmask)^2 per (b,c)
__device__ float g_pos[BB * CC];        // sum_t pmask per (b,c)
__device__ float g_st[1];               // sum (cas_s - cas_t)^2
__device__ float g_res[2];              // BCE partials: cls, be
__device__ unsigned int g_tile;         // dynamic tile counter

// ---------------- fused streaming kernel: dynamic tile queue ----------------
__global__ __launch_bounds__(256, 8) void main_kernel(
    const float* __restrict__ fa, const float* __restrict__ fb,
    const float* __restrict__ gt, const float* __restrict__ sup,
    const float* __restrict__ cas_s, const float* __restrict__ cas_t,
    const float* __restrict__ score_act, const float* __restrict__ score_bkg,
    const float* __restrict__ label) {
    const int tid = threadIdx.x;
    __shared__ float shbuf[16 * 16 * 4];   // feat: 16x16 float4; others: floats
    __shared__ unsigned int s_tile;

    for (;;) {
        if (tid == 0) s_tile = atomicAdd(&g_tile, 1u);
        __syncthreads();
        const unsigned int tile = s_tile;
        __syncthreads();                   // shbuf/s_tile safe to reuse
        if (tile >= NTILES) return;

        if (tile == 0) {
            // ---- BCE tile: input-only, overlaps the big stream ----
            __shared__ float lsum[BB];
            if (tid < BB) lsum[tid] = 0.f;
            __syncthreads();
            for (int i = tid; i < BB * CC; i += 256)
                atomicAdd(&lsum[i / CC], label[i]);
            __syncthreads();

            float acc_cls = 0.f, acc_be = 0.f;
            const float tb = 1.0f / CC;
            for (int i = tid; i < BB * CC; i += 256) {
                float p = score_act[i];
                p = fminf(fmaxf(p, EPS_C), 1.0f - EPS_C);
                float t = label[i] / lsum[i / CC];
                acc_cls += t * logf(p) + (1.0f - t) * log1pf(-p);

                float q = score_bkg[i];
                q = fminf(fmaxf(q, EPS_C), 1.0f - EPS_C);
                acc_be += tb * logf(q) + (1.0f - tb) * log1pf(-q);
            }
            float* sh = shbuf;
            sh[tid] = acc_cls;
            sh[256 + tid] = acc_be;
            __syncthreads();
            for (int s = 128; s > 0; s >>= 1) {
                if (tid < s) {
                    sh[tid] += sh[tid + s];
                    sh[256 + tid] += sh[256 + tid + s];
                }
                __syncthreads();
            }
            if (tid == 0) {
                g_res[0] = sh[0];
                g_res[1] = sh[256];
            }
            __syncthreads();
        } else if (tile <= FEAT_TILES) {
            // ---- feat: tile owns (tensor, b, 64-float d-strip) over ALL t ----
            const int fz = tile - 1;
            const int dch = fz & (FEAT_NDCH - 1);
            const int z = fz >> 5;            // 0..31
            const int tensor = z >> 4;
            const int b = z & 15;
            const float* __restrict__ f = tensor ? fb : fa;

            const int lane16 = tid & 15;      // d-lane (float4)
            const int rg = tid >> 4;          // row-group 0..15
            const int d0 = dch * FEAT_DCHUNK + lane16 * 4;
            const float4* __restrict__ p =
                (const float4*)(f + (size_t)b * TT * DD + (size_t)rg * DD + d0);

            float4 acc = make_float4(0.f, 0.f, 0.f, 0.f);
#pragma unroll 16
            for (int t = 0; t < TT / 16; t++) {           // 128 iterations
                float4 v = __ldcs(p + (size_t)t * (16 * DD / 4));
                acc.x += v.x; acc.y += v.y; acc.z += v.z; acc.w += v.w;
            }

            float4* sh4 = (float4*)shbuf;     // [16 rg][16 lane]
            sh4[rg * 16 + lane16] = acc;
            __syncthreads();

            float partial = 0.f;
            if (tid < 16) {
                float4 c = sh4[tid];
#pragma unroll
                for (int r = 1; r < 16; r++) {
                    float4 v = sh4[r * 16 + tid];
                    c.x += v.x; c.y += v.y; c.z += v.z; c.w += v.w;
                }
                const float invT = 1.0f / TT;
                float x = c.x * invT, y = c.y * invT, zz = c.z * invT, w = c.w * invT;
                partial = x * x + y * y + zz * zz + w * w;
            }
            if (tid < 32) {
#pragma unroll
                for (int o = 16; o > 0; o >>= 1)
                    partial += __shfl_xor_sync(0xFFFFFFFFu, partial, o);
                if (tid == 0) atomicAdd(&g_n2[z], partial);
            }
            __syncthreads();
        } else {
            // ---- [B,T,C] streams: sup / pos / st ----
            const int i = tile - 1 - FEAT_TILES;   // 0..511
            const int b = i >> 5;
            const int tci = i & 31;
            const int half = tid >> 7;        // 0 or 1
            const int c = tid & 127;
            const int t0 = tci * 64 + half * 32;

            float sq = 0.f, pos = 0.f, st = 0.f;
            if (c < CC) {
                size_t base = (size_t)b * TT * CC + (size_t)t0 * CC + c;
#pragma unroll 4
                for (int t = 0; t < 32; t++) {
                    size_t o = base + (size_t)t * CC;
                    float g = __ldcs(gt + o);
                    float s = __ldcs(sup + o);
                    float x = __ldcs(cas_s + o);
                    float y = __ldcs(cas_t + o);
                    float pm = (g > 0.5f) ? 1.f : 0.f;
                    float d = s - pm;
                    sq += d * d;
                    pos += pm;
                    float e = x - y;
                    st += e * e;
                }
                atomicAdd(&g_sq[b * CC + c], sq);
                atomicAdd(&g_pos[b * CC + c], pos);
            }
            float* sh = shbuf;
            sh[tid] = st;
            __syncthreads();
            for (int s = 128; s > 0; s >>= 1) {
                if (tid < s) sh[tid] += sh[tid + s];
                __syncthreads();
            }
            if (tid == 0) atomicAdd(g_st, sh[0]);
            __syncthreads();
        }
    }
}

// ---------------- final: one block, scratch-only (L2-hot) -------------------
__device__ __forceinline__ float block_reduce_256(float v, float* red) {
    int tid = threadIdx.x;
    red[tid] = v;
    __syncthreads();
    for (int s = 128; s > 0; s >>= 1) {
        if (tid < s) red[tid] += red[tid + s];
        __syncthreads();
    }
    float r = red[0];
    __syncthreads();
    return r;
}

__global__ __launch_bounds__(256) void final_kernel(float* __restrict__ out) {
    const int tid = threadIdx.x;
    __shared__ float red[256];

    // ---- loss_sup; zero g_sq/g_pos after reading ----
    float acc_sup = 0.f, acc_cnt = 0.f;
    for (int i = tid; i < BB * CC; i += 256) {
        float pv = g_pos[i];
        float qv = g_sq[i];
        if (pv > 0.f) {
            acc_sup += sqrtf(qv);
            acc_cnt += 1.f;
        }
        g_pos[i] = 0.f;
        g_sq[i] = 0.f;
    }
    float sum_sup = block_reduce_256(acc_sup, red);
    float sum_cnt = block_reduce_256(acc_cnt, red);

    // ---- loss_um from g_n2 (16 lanes active); zero g_n2 after read ----
    float um_part = 0.f;
    if (tid < BB) {
        float an = sqrtf(g_n2[tid]);
        float bn = sqrtf(g_n2[BB + tid]);
        float la = fmaxf(MARGIN - an, 0.f);
        float v = la + bn;
        um_part = v * v;
    }
    __syncthreads();
    if (tid < 2 * BB) g_n2[tid] = 0.f;
    float sum_um = block_reduce_256(um_part, red);

    if (tid == 0) {
        float st_sum = g_st[0];
        g_st[0] = 0.f;
        g_tile = 0u;                      // reset queue for next replay

        float loss_cls = -g_res[0] / (float)(BB * CC);
        float loss_be  = -g_res[1] / (float)(BB * CC);
        float loss_um  = sum_um / (float)BB;
        float loss_sup = sum_sup / fmaxf(sum_cnt, 1.0f);
        float loss_st  = st_sum / (float)(BB * TT * CC);

        float total = loss_cls + ALPHA * loss_um + loss_be + loss_sup + loss_st;
        out[0] = total;
        out[1] = loss_cls;
        out[2] = loss_be;
        out[3] = loss_um;
        out[4] = loss_sup;
        out[5] = loss_st;
    }
}

// ---------------- launch ----------------
extern "C" void kernel_launch(void* const* d_in, const int* in_sizes, int n_in,
                              void* d_out, int out_size) {
    const float* score_act = (const float*)d_in[0];
    const float* score_bkg = (const float*)d_in[1];
    const float* feat_act  = (const float*)d_in[2];
    const float* feat_bkg  = (const float*)d_in[3];
    const float* label     = (const float*)d_in[4];
    const float* gt        = (const float*)d_in[5];
    const float* sup_cas   = (const float*)d_in[6];
    const float* cas_s     = (const float*)d_in[7];
    const float* cas_t     = (const float*)d_in[8];

    main_kernel<<<GRID_BLOCKS, 256>>>(
        feat_act, feat_bkg, gt, sup_cas, cas_s, cas_t,
        score_act, score_bkg, label);
    final_kernel<<<1, 256>>>((float*)d_out);
}